// round 3
// baseline (speedup 1.0000x reference)
#include <cuda_runtime.h>
#include <math.h>

#define CH 128
#define CH4 (CH / 4)

// Reparameterization constants (match reference, fp64 -> fp32 rounding)
#define PED_F         1.4551915228366852e-11f   // 2^-36, exact in fp32
#define GAMMA_BOUND_F 3.814697265625e-06f       // 2^-18, exact in fp32
#define BETA_BOUND_F  1.0000072759311444e-03f   // sqrt(1e-6 + 2^-36)

// Static device scratch (no allocations allowed)
__device__ float g_b[CH];
__device__ float g_dv[CH];          // diagonal value per channel (valid if g_diag_ok)
__device__ int   g_diag_ok;         // 1 if g is exactly diagonal
__device__ int   g_cnt[CH];
__device__ int   g_eidx[CH * CH];
__device__ float g_eval[CH * CH];

// ---------------------------------------------------------------------------
// Fused prepass (single block, one launch):
//   - b[i] from beta (exact reference arithmetic)
//   - sparse compaction of g rows (warp-per-row, 8 warps x 16 rows)
//   - diagonal flag + per-channel diagonal value, all in-block
// ---------------------------------------------------------------------------
__global__ void __launch_bounds__(256) gdn_prepass(
    const float* __restrict__ beta, const float* __restrict__ gamma) {
    __shared__ int s_ok;
    int tid  = threadIdx.x;
    int w    = tid >> 5;
    int lane = tid & 31;

    if (tid == 0) s_ok = 1;
    if (tid < CH) {
        float bb = fmaxf(beta[tid], BETA_BOUND_F);
        g_b[tid] = bb * bb - PED_F;
    }

    // 8 warps, each compacts 16 rows
    for (int r = 0; r < 16; ++r) {
        int row = w * 16 + r;
        float4 g4 = ((const float4*)(gamma + (long long)row * CH))[lane];
        float gin[4] = {g4.x, g4.y, g4.z, g4.w};

        float vals[4];
        int   idxs[4];
        int m = 0;
#pragma unroll
        for (int k = 0; k < 4; ++k) {
            float g = fmaxf(gin[k], GAMMA_BOUND_F);
            g = g * g - PED_F;
            if (g != 0.0f) { vals[m] = g; idxs[m] = lane * 4 + k; m++; }
        }

        // exclusive warp scan of m
        int off = m;
#pragma unroll
        for (int d = 1; d < 32; d <<= 1) {
            int o = __shfl_up_sync(0xffffffffu, off, d);
            if (lane >= d) off += o;
        }
        int total = __shfl_sync(0xffffffffu, off, 31);
        off -= m;

        for (int t = 0; t < m; ++t) {
            g_eidx[row * CH + off + t] = idxs[t];
            g_eval[row * CH + off + t] = vals[t];
        }
        if (lane == 31) g_cnt[row] = total;
    }
    __syncthreads();

    // diagonal check + dv extraction (threads 0..127, reading just-written glob)
    if (tid < CH) {
        int   cnt = g_cnt[tid];
        int   idx = g_eidx[tid * CH];
        float v   = g_eval[tid * CH];
        bool diag = (cnt == 1) && (idx == tid);
        g_dv[tid] = diag ? v : 0.0f;
        if (!diag) atomicAnd(&s_ok, 0);
    }
    __syncthreads();
    if (tid == 0) g_diag_ok = s_ok;
}

// ---------------------------------------------------------------------------
// Main kernel. Fast path (g diagonal): pure elementwise float4 stream with
// streaming cache hints and a 4-deep load pipeline. Fallback: general sparse.
// ---------------------------------------------------------------------------
__global__ void __launch_bounds__(256)
gdn_main(const float* __restrict__ x, float* __restrict__ out, long long n4) {
    const long long stride = (long long)gridDim.x * blockDim.x;   // multiple of 32
    long long i = (long long)blockIdx.x * blockDim.x + threadIdx.x;

    const int c4 = (int)(i & (CH4 - 1));   // fixed channel-group (stride % 32 == 0)
    const int c0 = c4 * 4;

    const float4* __restrict__ x4   = (const float4*)x;
    float4* __restrict__       out4 = (float4*)out;

    if (g_diag_ok) {
        const float4 b4 = ((const float4*)g_b)[c4];
        const float4 v4 = ((const float4*)g_dv)[c4];

#define GDN_ELT(o, xa)                                              \
        o.x = xa.x * rsqrtf(fmaf(v4.x, xa.x * xa.x, b4.x));         \
        o.y = xa.y * rsqrtf(fmaf(v4.y, xa.y * xa.y, b4.y));         \
        o.z = xa.z * rsqrtf(fmaf(v4.z, xa.z * xa.z, b4.z));         \
        o.w = xa.w * rsqrtf(fmaf(v4.w, xa.w * xa.w, b4.w));

        // 4-deep software pipeline: 4 front-batched streaming loads
        for (; i + 3 * stride < n4; i += 4 * stride) {
            float4 xa = __ldcs(&x4[i]);
            float4 xb = __ldcs(&x4[i + stride]);
            float4 xc = __ldcs(&x4[i + 2 * stride]);
            float4 xd = __ldcs(&x4[i + 3 * stride]);
            float4 oa, ob, oc, od;
            GDN_ELT(oa, xa)
            GDN_ELT(ob, xb)
            GDN_ELT(oc, xc)
            GDN_ELT(od, xd)
            __stcs(&out4[i],              oa);
            __stcs(&out4[i + stride],     ob);
            __stcs(&out4[i + 2 * stride], oc);
            __stcs(&out4[i + 3 * stride], od);
        }
        for (; i < n4; i += stride) {
            float4 xa = __ldcs(&x4[i]);
            float4 oa;
            GDN_ELT(oa, xa)
            __stcs(&out4[i], oa);
        }
#undef GDN_ELT
    } else {
        // General sparse fallback (correct for any g); x row re-read from L2.
        for (; i < n4; i += stride) {
            long long row  = i >> 5;              // / CH4
            const float* xr = x + row * CH;
            float4 o;
            float r[4];
#pragma unroll
            for (int k = 0; k < 4; ++k) {
                int   c   = c0 + k;
                float acc = g_b[c];
                int   cnt = g_cnt[c];
                for (int e = 0; e < cnt; ++e) {
                    float t = xr[g_eidx[c * CH + e]];
                    acc = fmaf(g_eval[c * CH + e], t * t, acc);
                }
                r[k] = xr[c] * rsqrtf(acc);
            }
            o.x = r[0]; o.y = r[1]; o.z = r[2]; o.w = r[3];
            out4[i] = o;
        }
    }
}

// ---------------------------------------------------------------------------
extern "C" void kernel_launch(void* const* d_in, const int* in_sizes, int n_in,
                              void* d_out, int out_size) {
    const float* x     = (const float*)d_in[0];
    const float* beta  = (const float*)d_in[1];
    const float* gamma = (const float*)d_in[2];
    float*       out   = (float*)d_out;

    long long nelem = (long long)in_sizes[0];
    long long n4    = nelem / 4;

    gdn_prepass<<<1, 256>>>(beta, gamma);

    // 148 SMs x 8 blocks of 256 threads
    int blocks = 148 * 8;
    gdn_main<<<blocks, 256>>>(x, out, n4);
}

// round 4
// speedup vs baseline: 1.0566x; 1.0566x over previous
#include <cuda_runtime.h>
#include <math.h>

#define CH 128
#define CH4 (CH / 4)

// Reparameterization constants (match reference, fp64 -> fp32 rounding)
#define PED_F         1.4551915228366852e-11f   // 2^-36, exact in fp32
#define GAMMA_BOUND_F 3.814697265625e-06f       // 2^-18, exact in fp32
#define BETA_BOUND_F  1.0000072759311444e-03f   // sqrt(1e-6 + 2^-36)

// Static device scratch (no allocations allowed)
__device__ float g_b[CH];
__device__ float g_dv[CH];          // diagonal value per channel (if simple)
__device__ int   g_simple[CH];      // row i is exactly {(i, dv)} sparse
__device__ int   g_cnt[CH];
__device__ int   g_eidx[CH * CH];
__device__ float g_eval[CH * CH];

// ---------------------------------------------------------------------------
// Prepass: ONE launch, 32 blocks x 128 threads, warp-per-row.
//   - b[i] (exact reference arithmetic)
//   - sparse compaction of g row
//   - per-row simple flag + diagonal value (via in-warp shuffle broadcast)
// ---------------------------------------------------------------------------
__global__ void __launch_bounds__(128) gdn_prepass(
    const float* __restrict__ beta, const float* __restrict__ gamma) {
    int lane = threadIdx.x & 31;
    int row  = blockIdx.x * 4 + (threadIdx.x >> 5);   // 32 blocks x 4 warps
    if (row >= CH) return;

    if (lane == 0) {
        float bb = fmaxf(beta[row], BETA_BOUND_F);
        g_b[row] = bb * bb - PED_F;
    }

    float4 g4 = ((const float4*)(gamma + (long long)row * CH))[lane];
    float gin[4] = {g4.x, g4.y, g4.z, g4.w};

    float vals[4];
    int   idxs[4];
    int m = 0;
#pragma unroll
    for (int k = 0; k < 4; ++k) {
        float g = fmaxf(gin[k], GAMMA_BOUND_F);
        g = g * g - PED_F;
        if (g != 0.0f) { vals[m] = g; idxs[m] = lane * 4 + k; m++; }
    }

    // exclusive warp scan of m
    int off = m;
#pragma unroll
    for (int d = 1; d < 32; d <<= 1) {
        int o = __shfl_up_sync(0xffffffffu, off, d);
        if (lane >= d) off += o;
    }
    int total = __shfl_sync(0xffffffffu, off, 31);
    off -= m;

    for (int t = 0; t < m; ++t) {
        g_eidx[row * CH + off + t] = idxs[t];
        g_eval[row * CH + off + t] = vals[t];
    }

    // broadcast first entry (lane whose exclusive offset is 0 and m>0)
    unsigned bal = __ballot_sync(0xffffffffu, (off == 0) && (m > 0));
    int src = bal ? (__ffs(bal) - 1) : 0;
    int   idx0 = __shfl_sync(0xffffffffu, m > 0 ? idxs[0] : -1, src);
    float val0 = __shfl_sync(0xffffffffu, m > 0 ? vals[0] : 0.0f, src);

    if (lane == 0) {
        g_cnt[row]    = total;
        int simple    = (total == 1) && (idx0 == row);
        g_simple[row] = simple;
        g_dv[row]     = simple ? val0 : 0.0f;
    }
}

// ---------------------------------------------------------------------------
// Main kernel. Per-thread path choice: if all 4 owned channels are "simple"
// (diagonal), pure elementwise float4 stream (streaming hints, 4-deep
// pipeline, 32-bit indexing). Otherwise general sparse fallback per channel.
// ---------------------------------------------------------------------------
__global__ void __launch_bounds__(256)
gdn_main(const float* __restrict__ x, float* __restrict__ out, unsigned n4) {
    const unsigned stride = gridDim.x * blockDim.x;        // multiple of 32
    unsigned i = blockIdx.x * blockDim.x + threadIdx.x;

    const int c4 = (int)(i & (CH4 - 1));   // fixed channel-group (stride % 32 == 0)
    const int c0 = c4 * 4;

    const float4* __restrict__ x4   = (const float4*)x;
    float4* __restrict__       out4 = (float4*)out;

    const int4 s4 = ((const int4*)g_simple)[c4];
    const bool fast = s4.x && s4.y && s4.z && s4.w;

    if (fast) {
        const float4 b4 = ((const float4*)g_b)[c4];
        const float4 v4 = ((const float4*)g_dv)[c4];

#define GDN_ELT(o, xa)                                              \
        o.x = xa.x * rsqrtf(fmaf(v4.x, xa.x * xa.x, b4.x));         \
        o.y = xa.y * rsqrtf(fmaf(v4.y, xa.y * xa.y, b4.y));         \
        o.z = xa.z * rsqrtf(fmaf(v4.z, xa.z * xa.z, b4.z));         \
        o.w = xa.w * rsqrtf(fmaf(v4.w, xa.w * xa.w, b4.w));

        for (; i + 3 * stride < n4; i += 4 * stride) {
            float4 xa = __ldcs(&x4[i]);
            float4 xb = __ldcs(&x4[i + stride]);
            float4 xc = __ldcs(&x4[i + 2 * stride]);
            float4 xd = __ldcs(&x4[i + 3 * stride]);
            float4 oa, ob, oc, od;
            GDN_ELT(oa, xa)
            GDN_ELT(ob, xb)
            GDN_ELT(oc, xc)
            GDN_ELT(od, xd)
            __stcs(&out4[i],              oa);
            __stcs(&out4[i + stride],     ob);
            __stcs(&out4[i + 2 * stride], oc);
            __stcs(&out4[i + 3 * stride], od);
        }
        for (; i < n4; i += stride) {
            float4 xa = __ldcs(&x4[i]);
            float4 oa;
            GDN_ELT(oa, xa)
            __stcs(&out4[i], oa);
        }
#undef GDN_ELT
    } else {
        // General sparse fallback (correct for any g); x row re-read from L2.
        for (; i < n4; i += stride) {
            unsigned row = i >> 5;                 // / CH4
            const float* xr = x + (size_t)row * CH;
            float4 o;
            float r[4];
#pragma unroll
            for (int k = 0; k < 4; ++k) {
                int   c   = c0 + k;
                float acc = g_b[c];
                int   cnt = g_cnt[c];
                for (int e = 0; e < cnt; ++e) {
                    float t = xr[g_eidx[c * CH + e]];
                    acc = fmaf(g_eval[c * CH + e], t * t, acc);
                }
                r[k] = xr[c] * rsqrtf(acc);
            }
            o.x = r[0]; o.y = r[1]; o.z = r[2]; o.w = r[3];
            out4[i] = o;
        }
    }
}

// ---------------------------------------------------------------------------
extern "C" void kernel_launch(void* const* d_in, const int* in_sizes, int n_in,
                              void* d_out, int out_size) {
    const float* x     = (const float*)d_in[0];
    const float* beta  = (const float*)d_in[1];
    const float* gamma = (const float*)d_in[2];
    float*       out   = (float*)d_out;

    unsigned n4 = (unsigned)(in_sizes[0] / 4);

    gdn_prepass<<<32, 128>>>(beta, gamma);

    int blocks = 148 * 8;
    gdn_main<<<blocks, 256>>>(x, out, n4);
}